// round 6
// baseline (speedup 1.0000x reference)
#include <cuda_runtime.h>
#include <cuda_bf16.h>
#include <math.h>
#include <stdint.h>

// Fixed problem shapes
#define M_TOT 8192
#define NREL  64
#define D     128
#define TM    64            // m per tile -> 128 A rows (u rows 0..63, v rows 64..127)
#define THREADS 256
#define NBLK  148
#define CHUNK 56            // ceil(8192/148)
#define REG_LAMBDA 1e-5f

// ---------------- device scratch (zero-init at load; each call resets at end) ----------------
__device__ int g_cnt[NREL];
__device__ int g_bucket[NREL * M_TOT];      // 2 MB
__device__ float g_val[M_TOT];
__device__ unsigned int g_tilectr;
__device__ unsigned int g_bar1;
__device__ unsigned int g_bar2;

// ---------------- helpers ----------------
static __device__ __forceinline__ void split_bf(float x, unsigned short& hi, unsigned short& lo) {
    __nv_bfloat16 h = __float2bfloat16(x);
    float hf = __bfloat162float(h);
    __nv_bfloat16 l = __float2bfloat16(x - hf);
    hi = __bfloat16_as_ushort(h);
    lo = __bfloat16_as_ushort(l);
}

// mma.sync m16n8k16 row.col f32 <- bf16*bf16 + f32 (valid on plain sm_103)
static __device__ __forceinline__ void mma_bf16(float c[4],
                                                uint32_t a0, uint32_t a1,
                                                uint32_t a2, uint32_t a3,
                                                uint32_t b0, uint32_t b1) {
    asm("mma.sync.aligned.m16n8k16.row.col.f32.bf16.bf16.f32 "
        "{%0,%1,%2,%3}, {%4,%5,%6,%7}, {%8,%9}, {%0,%1,%2,%3};"
        : "+f"(c[0]), "+f"(c[1]), "+f"(c[2]), "+f"(c[3])
        : "r"(a0), "r"(a1), "r"(a2), "r"(a3), "r"(b0), "r"(b1));
}

// ---------------- smem layout ----------------
#define ASTRIDE 264                          // A row stride in bytes (128 bf16 + pad)
#define OFF_AHI 0                            // 128 * 264 = 33792
#define OFF_ALO 33792                        // -> 67584
#define OFF_BF  67584                        // B fragments: 8*16*32*16B = 65536 -> 133120
#define OFF_RSH 133120                       // 512
#define OFF_SC  133632                       // 512
#define OFF_REG 134144                       // 256
#define OFF_MSH 134400
#define OFF_HIX 134656
#define OFF_PIX 134912
#define OFF_NIX 135168
#define OFF_CTL 135424                       // {rel, start, cnt}
#define OFF_RSQ 135440
#define OFF_SCNT 135488                      // 64 ints
#define OFF_STP  135744                      // 65 ints
#define SMEM_SZ  136064

__global__ void __launch_bounds__(THREADS, 1) k_all(
    const int*   __restrict__ h,
    const int*   __restrict__ r,
    const int*   __restrict__ pos_t,
    const int*   __restrict__ neg_t,
    const float* __restrict__ ent,
    const float* __restrict__ rel_emb,
    const float* __restrict__ rel_w,
    float*       __restrict__ out)
{
    extern __shared__ char smem[];
    int tid = threadIdx.x;
    int w = tid >> 5, l = tid & 31;
    int gid = l >> 2, tig = l & 3;

    float* rsh   = (float*)(smem + OFF_RSH);
    float* sc    = (float*)(smem + OFF_SC);
    float* regsh = (float*)(smem + OFF_REG);
    int*   msh   = (int*)(smem + OFF_MSH);
    int*   hix   = (int*)(smem + OFF_HIX);
    int*   pix   = (int*)(smem + OFF_PIX);
    int*   nix   = (int*)(smem + OFF_NIX);
    int*   scnt  = (int*)(smem + OFF_SCNT);
    int*   stp   = (int*)(smem + OFF_STP);

    // ---------- Phase A: parallel bucket scatter (the scatter IS the histogram) ----------
    {
        int m = blockIdx.x * CHUNK + tid;
        if (tid < CHUNK && m < M_TOT) {
            int rel = r[m];
            int p = atomicAdd(&g_cnt[rel], 1);
            g_bucket[rel * M_TOT + p] = m;
        }
    }

    // ---------- grid barrier 1 (full) ----------
    __threadfence();
    __syncthreads();
    if (tid == 0) {
        atomicAdd(&g_bar1, 1u);
        while (atomicAdd(&g_bar1, 0u) < NBLK) __nanosleep(64);
    }
    __syncthreads();

    // ---------- Phase B: redundant per-block plan ----------
    if (tid < NREL) scnt[tid] = atomicAdd(&g_cnt[tid], 0);
    __syncthreads();
    if (tid == 0) {
        int acc = 0;
        for (int rel = 0; rel < NREL; rel++) {
            stp[rel] = acc;
            acc += (scnt[rel] + TM - 1) / TM;
        }
        stp[NREL] = acc;
    }
    __syncthreads();
    int ntiles = stp[NREL];

    // ---------- tile loop ----------
    for (;;) {
        if (tid == 0) {
            int tile = (int)atomicAdd(&g_tilectr, 1u);
            int rel = -1, start = 0, cnt = 0;
            if (tile < ntiles) {
                rel = 0;
                while (stp[rel + 1] <= tile) rel++;
                start = (tile - stp[rel]) * TM;
                cnt = min(TM, scnt[rel] - start);
            }
            ((int*)(smem + OFF_CTL))[0] = rel;
            ((int*)(smem + OFF_CTL))[1] = start;
            ((int*)(smem + OFF_CTL))[2] = cnt;
        }
        __syncthreads();
        int rel   = ((int*)(smem + OFF_CTL))[0];
        int start = ((int*)(smem + OFF_CTL))[1];
        int cnt   = ((int*)(smem + OFF_CTL))[2];
        if (rel < 0) break;

        // stage indices + relation embedding
        if (tid < TM && tid < cnt) {
            int mo = g_bucket[rel * M_TOT + start + tid];
            msh[tid] = mo;
            hix[tid] = h[mo];
            pix[tid] = pos_t[mo];
            nix[tid] = neg_t[mo];
        }
        if (tid < D) rsh[tid] = rel_emb[rel * D + tid];
        __syncthreads();

        // rsq on warp 4
        if (w == 4) {
            float s = 0.f;
            #pragma unroll
            for (int q = 0; q < 4; q++) { float x = rsh[q * 32 + l]; s += x * x; }
            #pragma unroll
            for (int o = 16; o; o >>= 1) s += __shfl_xor_sync(0xffffffffu, s, o);
            if (l == 0) *(float*)(smem + OFF_RSQ) = s;
        }

        // ---- gather + bf16 split + stage A (u at row m, v at row 64+m) ----
        #pragma unroll
        for (int it = 0; it < 8; it++) {
            int m = w + 8 * it;
            char* puh = smem + OFF_AHI + m * ASTRIDE + 8 * l;
            char* pul = smem + OFF_ALO + m * ASTRIDE + 8 * l;
            char* pvh = smem + OFF_AHI + (64 + m) * ASTRIDE + 8 * l;
            char* pvl = smem + OFF_ALO + (64 + m) * ASTRIDE + 8 * l;
            if (m < cnt) {
                float4 h4 = ((const float4*)(ent + (size_t)hix[m] * D))[l];
                float4 p4 = ((const float4*)(ent + (size_t)pix[m] * D))[l];
                float4 n4 = ((const float4*)(ent + (size_t)nix[m] * D))[l];
                float u0 = h4.x - p4.x, u1 = h4.y - p4.y, u2 = h4.z - p4.z, u3 = h4.w - p4.w;
                float v0 = h4.x - n4.x, v1 = h4.y - n4.y, v2 = h4.z - n4.z, v3 = h4.w - n4.w;
                float sq = h4.x*h4.x + h4.y*h4.y + h4.z*h4.z + h4.w*h4.w
                         + p4.x*p4.x + p4.y*p4.y + p4.z*p4.z + p4.w*p4.w
                         + n4.x*n4.x + n4.y*n4.y + n4.z*n4.z + n4.w*n4.w;
                unsigned short uh[4], ul[4], vh[4], vl[4];
                split_bf(u0, uh[0], ul[0]); split_bf(u1, uh[1], ul[1]);
                split_bf(u2, uh[2], ul[2]); split_bf(u3, uh[3], ul[3]);
                split_bf(v0, vh[0], vl[0]); split_bf(v1, vh[1], vl[1]);
                split_bf(v2, vh[2], vl[2]); split_bf(v3, vh[3], vl[3]);
                *(uint2*)puh = make_uint2((uint32_t)uh[0] | ((uint32_t)uh[1] << 16),
                                          (uint32_t)uh[2] | ((uint32_t)uh[3] << 16));
                *(uint2*)pul = make_uint2((uint32_t)ul[0] | ((uint32_t)ul[1] << 16),
                                          (uint32_t)ul[2] | ((uint32_t)ul[3] << 16));
                *(uint2*)pvh = make_uint2((uint32_t)vh[0] | ((uint32_t)vh[1] << 16),
                                          (uint32_t)vh[2] | ((uint32_t)vh[3] << 16));
                *(uint2*)pvl = make_uint2((uint32_t)vl[0] | ((uint32_t)vl[1] << 16),
                                          (uint32_t)vl[2] | ((uint32_t)vl[3] << 16));
                #pragma unroll
                for (int o = 16; o; o >>= 1) sq += __shfl_xor_sync(0xffffffffu, sq, o);
                if (l == 0) regsh[m] = sq;
            } else {
                uint2 z = make_uint2(0u, 0u);
                *(uint2*)puh = z; *(uint2*)pul = z;
                *(uint2*)pvh = z; *(uint2*)pvl = z;
            }
        }

        // ---- W -> B fragments in smem (coalesced f32 read from L2) ----
        // frag entry (ks,nt,lane): uint4 {b0_hi, b1_hi, b0_lo, b1_lo}; value W[k][j]
        // maps to ks=k>>4, tig=(k>>1)&3, khigh=(k>>3)&1, klow=k&1, nt=j>>3, lane=4*(j&7)+tig
        {
            const float4* Wg = (const float4*)(rel_w + (size_t)rel * D * D);
            #pragma unroll
            for (int idx = tid; idx < D * (D / 4); idx += THREADS) {
                int k  = idx >> 5;
                int j4 = idx & 31;
                float4 wv = Wg[idx];
                int ks    = k >> 4;
                int ktig  = (k >> 1) & 3;
                uint32_t comb = (uint32_t)(((k >> 3) & 1) * 4 + (k & 1) * 2);
                float vals[4] = {wv.x, wv.y, wv.z, wv.w};
                #pragma unroll
                for (int c = 0; c < 4; c++) {
                    int j = 4 * j4 + c;
                    int nt = j >> 3, jg = j & 7;
                    unsigned short hi, lo;
                    split_bf(vals[c], hi, lo);
                    uint32_t byte = (uint32_t)(((ks * 16 + nt) * 32 + 4 * jg + ktig) * 16) + comb;
                    *(unsigned short*)(smem + OFF_BF + byte)     = hi;
                    *(unsigned short*)(smem + OFF_BF + byte + 8) = lo;
                }
            }
        }
        __syncthreads();

        // ---- MMA: warp w computes D rows 16w..16w+15, all 128 cols (3-pass bf16 split) ----
        const char* A0h = smem + OFF_AHI + (16 * w + gid) * ASTRIDE + 4 * tig;
        const char* A1h = A0h + 8 * ASTRIDE;
        const char* A0l = smem + OFF_ALO + (16 * w + gid) * ASTRIDE + 4 * tig;
        const char* A1l = A0l + 8 * ASTRIDE;
        const uint4* bfr = (const uint4*)(smem + OFF_BF);

        float c[16][4];
        #pragma unroll
        for (int nt = 0; nt < 16; nt++)
            #pragma unroll
            for (int i = 0; i < 4; i++) c[nt][i] = 0.f;

        for (int ks = 0; ks < 8; ks++) {
            uint32_t ah0 = *(const uint32_t*)(A0h + 32 * ks);
            uint32_t ah1 = *(const uint32_t*)(A1h + 32 * ks);
            uint32_t ah2 = *(const uint32_t*)(A0h + 32 * ks + 16);
            uint32_t ah3 = *(const uint32_t*)(A1h + 32 * ks + 16);
            uint32_t al0 = *(const uint32_t*)(A0l + 32 * ks);
            uint32_t al1 = *(const uint32_t*)(A1l + 32 * ks);
            uint32_t al2 = *(const uint32_t*)(A0l + 32 * ks + 16);
            uint32_t al3 = *(const uint32_t*)(A1l + 32 * ks + 16);

            const uint4* bp = bfr + (ks * 16) * 32 + l;
            uint4 b[16];
            #pragma unroll
            for (int nt = 0; nt < 16; nt++) b[nt] = bp[nt * 32];   // conflict-free LDS.128

            #pragma unroll
            for (int nt = 0; nt < 16; nt++) {
                mma_bf16(c[nt], ah0, ah1, ah2, ah3, b[nt].x, b[nt].y);
                mma_bf16(c[nt], ah0, ah1, ah2, ah3, b[nt].z, b[nt].w);
                mma_bf16(c[nt], al0, al1, al2, al3, b[nt].x, b[nt].y);
            }
        }

        // ---- epilogue: add r_j, square, reduce over j ----
        float sA = 0.f, sB = 0.f;      // rows 16w+gid and 16w+8+gid
        #pragma unroll
        for (int nt = 0; nt < 16; nt++) {
            float r0 = rsh[8 * nt + 2 * tig];
            float r1 = rsh[8 * nt + 2 * tig + 1];
            float d0 = c[nt][0] + r0, d1 = c[nt][1] + r1;
            float d2 = c[nt][2] + r0, d3 = c[nt][3] + r1;
            sA += d0 * d0 + d1 * d1;
            sB += d2 * d2 + d3 * d3;
        }
        sA += __shfl_xor_sync(0xffffffffu, sA, 1);
        sA += __shfl_xor_sync(0xffffffffu, sA, 2);
        sB += __shfl_xor_sync(0xffffffffu, sB, 1);
        sB += __shfl_xor_sync(0xffffffffu, sB, 2);
        if (tig == 0) {
            sc[16 * w + gid]     = sA;
            sc[16 * w + 8 + gid] = sB;
        }
        __syncthreads();

        if (tid < TM && tid < cnt) {
            float x = 0.5f * (sc[tid] - sc[64 + tid]);              // pos - neg score
            float loss = fmaxf(-x, 0.f) + log1pf(expf(-fabsf(x)));  // softplus(-x)
            float rsq = *(float*)(smem + OFF_RSQ);
            g_val[msh[tid]] = loss + REG_LAMBDA * 0.5f * (regsh[tid] + rsq);
        }
        __syncthreads();
    }

    // ---------- grid barrier 2 (arrive; block 0 spins) ----------
    __threadfence();
    __syncthreads();
    if (tid == 0) atomicAdd(&g_bar2, 1u);
    if (blockIdx.x != 0) return;
    if (tid == 0) {
        while (atomicAdd(&g_bar2, 0u) < NBLK) __nanosleep(64);
    }
    __syncthreads();

    // ---------- final deterministic reduction (block 0) ----------
    double* sd = (double*)smem;                 // reuse dynamic smem
    double acc = 0.0;
    for (int i = tid; i < M_TOT; i += THREADS) acc += (double)g_val[i];
    sd[tid] = acc;
    __syncthreads();
    for (int s = THREADS / 2; s; s >>= 1) {
        if (tid < s) sd[tid] += sd[tid + s];
        __syncthreads();
    }
    if (tid == 0) out[0] = (float)(sd[0] / (double)M_TOT);

    // ---------- reset global state for next graph replay ----------
    if (tid < NREL) g_cnt[tid] = 0;
    if (tid == 0) { g_tilectr = 0; g_bar1 = 0; g_bar2 = 0; }
}

// ---------------- launch ----------------
extern "C" void kernel_launch(void* const* d_in, const int* in_sizes, int n_in,
                              void* d_out, int out_size) {
    const int*   h       = (const int*)d_in[0];
    const int*   r       = (const int*)d_in[1];
    const int*   pos_t   = (const int*)d_in[2];
    const int*   neg_t   = (const int*)d_in[3];
    const float* ent     = (const float*)d_in[4];
    const float* rel_emb = (const float*)d_in[5];
    const float* rel_w   = (const float*)d_in[6];
    float* out = (float*)d_out;

    cudaFuncSetAttribute(k_all, cudaFuncAttributeMaxDynamicSharedMemorySize, SMEM_SZ);
    k_all<<<NBLK, THREADS, SMEM_SZ>>>(h, r, pos_t, neg_t, ent, rel_emb, rel_w, out);
}

// round 7
// speedup vs baseline: 1.7641x; 1.7641x over previous
#include <cuda_runtime.h>
#include <cuda_bf16.h>
#include <math.h>
#include <stdint.h>

// Fixed problem shapes
#define M_TOT 8192
#define NREL  64
#define D     128
#define TM    64            // m per tile -> 128 A rows (u rows 0..63, v rows 64..127)
#define THREADS 256
#define NBLK  148
#define REG_LAMBDA 1e-5f

// ---------------- device scratch (zero-init at load; k_main resets at end) ----------------
__device__ int g_cnt[NREL];
__device__ int g_bucket[NREL * M_TOT];      // 2 MB
__device__ float g_val[M_TOT];
__device__ unsigned int g_tilectr;
__device__ unsigned int g_done;
// B fragments in mma.m16n8k16 register layout:
// g_bfrag[((rel*8 + ks)*16 + nt)*32 + lane] = {b0_hi, b1_hi, b0_lo, b1_lo}
__device__ uint4 g_bfrag[NREL * 8 * 16 * 32];   // 4 MB

// ---------------- helpers ----------------
static __device__ __forceinline__ void split_bf(float x, unsigned short& hi, unsigned short& lo) {
    __nv_bfloat16 h = __float2bfloat16(x);
    float hf = __bfloat162float(h);
    __nv_bfloat16 l = __float2bfloat16(x - hf);
    hi = __bfloat16_as_ushort(h);
    lo = __bfloat16_as_ushort(l);
}

// mma.sync m16n8k16 row.col f32 <- bf16*bf16 + f32 (valid on plain sm_103)
static __device__ __forceinline__ void mma_bf16(float c[4],
                                                uint32_t a0, uint32_t a1,
                                                uint32_t a2, uint32_t a3,
                                                uint32_t b0, uint32_t b1) {
    asm("mma.sync.aligned.m16n8k16.row.col.f32.bf16.bf16.f32 "
        "{%0,%1,%2,%3}, {%4,%5,%6,%7}, {%8,%9}, {%0,%1,%2,%3};"
        : "+f"(c[0]), "+f"(c[1]), "+f"(c[2]), "+f"(c[3])
        : "r"(a0), "r"(a1), "r"(a2), "r"(a3), "r"(b0), "r"(b1));
}

// ---------------- prep: parallel scatter (blocks 0-31) + W fragment build (blocks 32-287) ----------------
#define PREP_BLKS 288

__global__ void k_prep(const int* __restrict__ r, const float* __restrict__ rel_w) {
    int b = blockIdx.x;
    int tid = threadIdx.x;

    if (b < 32) {
        // bucket scatter: the scatter IS the histogram
        int m = b * 256 + tid;
        int rel = r[m];
        int p = atomicAdd(&g_cnt[rel], 1);
        g_bucket[rel * M_TOT + p] = m;
        return;
    }

    // fragment build: 262144 entries over 65536 threads -> 4 per thread, direct gmem->gmem
    int base = (b - 32) * 256 + tid;
    #pragma unroll
    for (int q = 0; q < 4; q++) {
        int e = base + q * 65536;
        int lane = e & 31;
        int nt   = (e >> 5) & 15;
        int ks   = (e >> 9) & 7;
        int rel  = e >> 12;
        int gid = lane >> 2, tig = lane & 3;
        int j  = 8 * nt + gid;
        int k0 = 16 * ks + 2 * tig;
        const float* W = rel_w + (size_t)rel * D * D;
        float w00 = __ldg(W + k0 * D + j);
        float w01 = __ldg(W + (k0 + 1) * D + j);
        float w10 = __ldg(W + (k0 + 8) * D + j);
        float w11 = __ldg(W + (k0 + 9) * D + j);
        unsigned short h00, l00, h01, l01, h10, l10, h11, l11;
        split_bf(w00, h00, l00); split_bf(w01, h01, l01);
        split_bf(w10, h10, l10); split_bf(w11, h11, l11);
        uint4 v;
        v.x = (uint32_t)h00 | ((uint32_t)h01 << 16);
        v.y = (uint32_t)h10 | ((uint32_t)h11 << 16);
        v.z = (uint32_t)l00 | ((uint32_t)l01 << 16);
        v.w = (uint32_t)l10 | ((uint32_t)l11 << 16);
        g_bfrag[e] = v;                        // coalesced STG.128
    }
}

// ---------------- main persistent kernel (R5 structure, proven) ----------------
#define ASTRIDE 264
#define OFF_AHI 0
#define OFF_ALO (128 * ASTRIDE)            // 33792
#define OFF_RSH (2 * 128 * ASTRIDE)        // 67584
#define OFF_SC  (OFF_RSH + 512)
#define OFF_REG (OFF_SC + 512)
#define OFF_MSH (OFF_REG + 256)
#define OFF_HIX (OFF_MSH + 256)
#define OFF_PIX (OFF_HIX + 256)
#define OFF_NIX (OFF_PIX + 256)
#define OFF_CTL (OFF_NIX + 256)            // {rel, start, cnt}
#define OFF_RSQ (OFF_CTL + 16)
#define OFF_SCNT (OFF_RSQ + 48)            // 64 ints
#define OFF_STP  (OFF_SCNT + 256)          // 65 ints
#define SMEM_SZ  (OFF_STP + 272)

__global__ void __launch_bounds__(THREADS, 1) k_main(
    const int*   __restrict__ h,
    const int*   __restrict__ pos_t,
    const int*   __restrict__ neg_t,
    const float* __restrict__ ent,
    const float* __restrict__ rel_emb,
    float*       __restrict__ out)
{
    extern __shared__ char smem[];
    int tid = threadIdx.x;
    int w = tid >> 5, l = tid & 31;
    int gid = l >> 2, tig = l & 3;

    float* rsh   = (float*)(smem + OFF_RSH);
    float* sc    = (float*)(smem + OFF_SC);
    float* regsh = (float*)(smem + OFF_REG);
    int*   msh   = (int*)(smem + OFF_MSH);
    int*   hix   = (int*)(smem + OFF_HIX);
    int*   pix   = (int*)(smem + OFF_PIX);
    int*   nix   = (int*)(smem + OFF_NIX);
    int*   scnt  = (int*)(smem + OFF_SCNT);
    int*   stp   = (int*)(smem + OFF_STP);

    // ---- per-block plan from counts (written by k_prep, stream-ordered) ----
    if (tid < NREL) scnt[tid] = g_cnt[tid];
    __syncthreads();
    if (tid == 0) {
        int acc = 0;
        for (int rel = 0; rel < NREL; rel++) {
            stp[rel] = acc;
            acc += (scnt[rel] + TM - 1) / TM;
        }
        stp[NREL] = acc;
    }
    __syncthreads();
    int ntiles = stp[NREL];

    // ---- tile loop ----
    for (;;) {
        if (tid == 0) {
            int tile = (int)atomicAdd(&g_tilectr, 1u);
            int rel = -1, start = 0, cnt = 0;
            if (tile < ntiles) {
                rel = 0;
                while (stp[rel + 1] <= tile) rel++;
                start = (tile - stp[rel]) * TM;
                cnt = min(TM, scnt[rel] - start);
            }
            ((int*)(smem + OFF_CTL))[0] = rel;
            ((int*)(smem + OFF_CTL))[1] = start;
            ((int*)(smem + OFF_CTL))[2] = cnt;
        }
        __syncthreads();
        int rel   = ((int*)(smem + OFF_CTL))[0];
        int start = ((int*)(smem + OFF_CTL))[1];
        int cnt   = ((int*)(smem + OFF_CTL))[2];
        if (rel < 0) break;

        // stage indices + relation embedding
        if (tid < TM && tid < cnt) {
            int mo = g_bucket[rel * M_TOT + start + tid];
            msh[tid] = mo;
            hix[tid] = h[mo];
            pix[tid] = pos_t[mo];
            nix[tid] = neg_t[mo];
        }
        if (tid < D) rsh[tid] = rel_emb[rel * D + tid];
        __syncthreads();

        // rsq on warp 4
        if (w == 4) {
            float s = 0.f;
            #pragma unroll
            for (int q = 0; q < 4; q++) { float x = rsh[q * 32 + l]; s += x * x; }
            #pragma unroll
            for (int o = 16; o; o >>= 1) s += __shfl_xor_sync(0xffffffffu, s, o);
            if (l == 0) *(float*)(smem + OFF_RSQ) = s;
        }

        // ---- gather + bf16 split + stage A (u at row m, v at row 64+m) ----
        #pragma unroll
        for (int it = 0; it < 8; it++) {
            int m = w + 8 * it;
            char* puh = smem + OFF_AHI + m * ASTRIDE + 8 * l;
            char* pul = smem + OFF_ALO + m * ASTRIDE + 8 * l;
            char* pvh = smem + OFF_AHI + (64 + m) * ASTRIDE + 8 * l;
            char* pvl = smem + OFF_ALO + (64 + m) * ASTRIDE + 8 * l;
            if (m < cnt) {
                float4 h4 = ((const float4*)(ent + (size_t)hix[m] * D))[l];
                float4 p4 = ((const float4*)(ent + (size_t)pix[m] * D))[l];
                float4 n4 = ((const float4*)(ent + (size_t)nix[m] * D))[l];
                float u0 = h4.x - p4.x, u1 = h4.y - p4.y, u2 = h4.z - p4.z, u3 = h4.w - p4.w;
                float v0 = h4.x - n4.x, v1 = h4.y - n4.y, v2 = h4.z - n4.z, v3 = h4.w - n4.w;
                float sq = h4.x*h4.x + h4.y*h4.y + h4.z*h4.z + h4.w*h4.w
                         + p4.x*p4.x + p4.y*p4.y + p4.z*p4.z + p4.w*p4.w
                         + n4.x*n4.x + n4.y*n4.y + n4.z*n4.z + n4.w*n4.w;
                unsigned short uh[4], ul[4], vh[4], vl[4];
                split_bf(u0, uh[0], ul[0]); split_bf(u1, uh[1], ul[1]);
                split_bf(u2, uh[2], ul[2]); split_bf(u3, uh[3], ul[3]);
                split_bf(v0, vh[0], vl[0]); split_bf(v1, vh[1], vl[1]);
                split_bf(v2, vh[2], vl[2]); split_bf(v3, vh[3], vl[3]);
                *(uint2*)puh = make_uint2((uint32_t)uh[0] | ((uint32_t)uh[1] << 16),
                                          (uint32_t)uh[2] | ((uint32_t)uh[3] << 16));
                *(uint2*)pul = make_uint2((uint32_t)ul[0] | ((uint32_t)ul[1] << 16),
                                          (uint32_t)ul[2] | ((uint32_t)ul[3] << 16));
                *(uint2*)pvh = make_uint2((uint32_t)vh[0] | ((uint32_t)vh[1] << 16),
                                          (uint32_t)vh[2] | ((uint32_t)vh[3] << 16));
                *(uint2*)pvl = make_uint2((uint32_t)vl[0] | ((uint32_t)vl[1] << 16),
                                          (uint32_t)vl[2] | ((uint32_t)vl[3] << 16));
                #pragma unroll
                for (int o = 16; o; o >>= 1) sq += __shfl_xor_sync(0xffffffffu, sq, o);
                if (l == 0) regsh[m] = sq;
            } else {
                uint2 z = make_uint2(0u, 0u);
                *(uint2*)puh = z; *(uint2*)pul = z;
                *(uint2*)pvh = z; *(uint2*)pvl = z;
            }
        }
        __syncthreads();

        // ---- MMA: warp w computes D rows 16w..16w+15, all 128 cols (3-pass bf16 split) ----
        const char* A0h = smem + OFF_AHI + (16 * w + gid) * ASTRIDE + 4 * tig;
        const char* A1h = A0h + 8 * ASTRIDE;
        const char* A0l = smem + OFF_ALO + (16 * w + gid) * ASTRIDE + 4 * tig;
        const char* A1l = A0l + 8 * ASTRIDE;

        float c[16][4];
        #pragma unroll
        for (int nt = 0; nt < 16; nt++)
            #pragma unroll
            for (int i = 0; i < 4; i++) c[nt][i] = 0.f;

        for (int ks = 0; ks < 8; ks++) {
            uint32_t ah0 = *(const uint32_t*)(A0h + 32 * ks);
            uint32_t ah1 = *(const uint32_t*)(A1h + 32 * ks);
            uint32_t ah2 = *(const uint32_t*)(A0h + 32 * ks + 16);
            uint32_t ah3 = *(const uint32_t*)(A1h + 32 * ks + 16);
            uint32_t al0 = *(const uint32_t*)(A0l + 32 * ks);
            uint32_t al1 = *(const uint32_t*)(A1l + 32 * ks);
            uint32_t al2 = *(const uint32_t*)(A0l + 32 * ks + 16);
            uint32_t al3 = *(const uint32_t*)(A1l + 32 * ks + 16);

            const uint4* bp = g_bfrag + ((size_t)(rel * 8 + ks) * 16) * 32 + l;
            uint4 b[16];
            #pragma unroll
            for (int nt = 0; nt < 16; nt++) b[nt] = bp[nt * 32];   // MLP=16, L2-hot

            #pragma unroll
            for (int nt = 0; nt < 16; nt++) {
                mma_bf16(c[nt], ah0, ah1, ah2, ah3, b[nt].x, b[nt].y);
                mma_bf16(c[nt], ah0, ah1, ah2, ah3, b[nt].z, b[nt].w);
                mma_bf16(c[nt], al0, al1, al2, al3, b[nt].x, b[nt].y);
            }
        }

        // ---- epilogue: add r_j, square, reduce over j ----
        float sA = 0.f, sB = 0.f;      // rows 16w+gid and 16w+8+gid
        #pragma unroll
        for (int nt = 0; nt < 16; nt++) {
            float r0 = rsh[8 * nt + 2 * tig];
            float r1 = rsh[8 * nt + 2 * tig + 1];
            float d0 = c[nt][0] + r0, d1 = c[nt][1] + r1;
            float d2 = c[nt][2] + r0, d3 = c[nt][3] + r1;
            sA += d0 * d0 + d1 * d1;
            sB += d2 * d2 + d3 * d3;
        }
        sA += __shfl_xor_sync(0xffffffffu, sA, 1);
        sA += __shfl_xor_sync(0xffffffffu, sA, 2);
        sB += __shfl_xor_sync(0xffffffffu, sB, 1);
        sB += __shfl_xor_sync(0xffffffffu, sB, 2);
        if (tig == 0) {
            sc[16 * w + gid]     = sA;
            sc[16 * w + 8 + gid] = sB;
        }
        __syncthreads();

        if (tid < TM && tid < cnt) {
            float x = 0.5f * (sc[tid] - sc[64 + tid]);              // pos - neg score
            float loss = fmaxf(-x, 0.f) + log1pf(expf(-fabsf(x)));  // softplus(-x)
            float rsq = *(float*)(smem + OFF_RSQ);
            g_val[msh[tid]] = loss + REG_LAMBDA * 0.5f * (regsh[tid] + rsq);
        }
        __syncthreads();
    }

    // ---------- last-block deterministic reduction + state reset ----------
    __shared__ bool amLast;
    __threadfence();
    __syncthreads();
    if (tid == 0) {
        unsigned int prev = atomicAdd(&g_done, 1u);
        amLast = (prev == (unsigned int)(gridDim.x - 1));
    }
    __syncthreads();
    if (!amLast) return;
    __threadfence();

    double* sd = (double*)smem;
    double acc = 0.0;
    for (int i = tid; i < M_TOT; i += THREADS) acc += (double)g_val[i];
    sd[tid] = acc;
    __syncthreads();
    for (int s = THREADS / 2; s; s >>= 1) {
        if (tid < s) sd[tid] += sd[tid + s];
        __syncthreads();
    }
    if (tid == 0) out[0] = (float)(sd[0] / (double)M_TOT);

    // reset for next graph replay
    if (tid < NREL) g_cnt[tid] = 0;
    if (tid == 0) { g_tilectr = 0; g_done = 0; }
}

// ---------------- launch ----------------
extern "C" void kernel_launch(void* const* d_in, const int* in_sizes, int n_in,
                              void* d_out, int out_size) {
    const int*   h       = (const int*)d_in[0];
    const int*   r       = (const int*)d_in[1];
    const int*   pos_t   = (const int*)d_in[2];
    const int*   neg_t   = (const int*)d_in[3];
    const float* ent     = (const float*)d_in[4];
    const float* rel_emb = (const float*)d_in[5];
    const float* rel_w   = (const float*)d_in[6];
    float* out = (float*)d_out;

    cudaFuncSetAttribute(k_main, cudaFuncAttributeMaxDynamicSharedMemorySize, SMEM_SZ);

    k_prep<<<PREP_BLKS, 256>>>(r, rel_w);
    k_main<<<NBLK, THREADS, SMEM_SZ>>>(h, pos_t, neg_t, ent, rel_emb, out);
}